// round 2
// baseline (speedup 1.0000x reference)
#include <cuda_runtime.h>

#define HID 400
#define SEQ 8192
#define DEPTH 32
#define ROW (DEPTH * HID)          // 12800 floats per timestep slab
#define TPB 128
#define NWARP (TPB / 32)

// Writes only row 0 of each timestep's (32, 400) slab with the scalar
//   s_t = softmax(h_t @ W^T + b)[0] * sigmoid(h_t @ D)
// Rows 1..31 are zero and handled by the memset node.
__global__ void __launch_bounds__(TPB)
top_kernel(const float* __restrict__ hid,
           const float* __restrict__ W,
           const float* __restrict__ b,
           const float* __restrict__ D,
           float* __restrict__ out)
{
    const int t = blockIdx.x;
    const float4* h4 = reinterpret_cast<const float4*>(hid + (size_t)t * HID);
    const float4* W4 = reinterpret_cast<const float4*>(W);
    const float4* D4 = reinterpret_cast<const float4*>(D);

    // 4 partial dot products over 100 float4 elements
    float a0 = 0.f, a1 = 0.f, a2 = 0.f, ad = 0.f;
    for (int i = threadIdx.x; i < HID / 4; i += TPB) {
        float4 x  = h4[i];
        float4 w0 = W4[i];
        float4 w1 = W4[HID / 4 + i];
        float4 w2 = W4[2 * (HID / 4) + i];
        float4 dd = D4[i];
        a0 += x.x * w0.x + x.y * w0.y + x.z * w0.z + x.w * w0.w;
        a1 += x.x * w1.x + x.y * w1.y + x.z * w1.z + x.w * w1.w;
        a2 += x.x * w2.x + x.y * w2.y + x.z * w2.z + x.w * w2.w;
        ad += x.x * dd.x + x.y * dd.y + x.z * dd.z + x.w * dd.w;
    }

    #pragma unroll
    for (int o = 16; o > 0; o >>= 1) {
        a0 += __shfl_down_sync(0xffffffffu, a0, o);
        a1 += __shfl_down_sync(0xffffffffu, a1, o);
        a2 += __shfl_down_sync(0xffffffffu, a2, o);
        ad += __shfl_down_sync(0xffffffffu, ad, o);
    }

    __shared__ float sm[4][NWARP];
    __shared__ float sval;
    const int lane = threadIdx.x & 31;
    const int w    = threadIdx.x >> 5;
    if (lane == 0) {
        sm[0][w] = a0; sm[1][w] = a1; sm[2][w] = a2; sm[3][w] = ad;
    }
    __syncthreads();

    if (threadIdx.x == 0) {
        float l0 = b[0], l1 = b[1], l2 = b[2], d = 0.f;
        #pragma unroll
        for (int i = 0; i < NWARP; i++) {
            l0 += sm[0][i]; l1 += sm[1][i]; l2 += sm[2][i]; d += sm[3][i];
        }
        float m  = fmaxf(l0, fmaxf(l1, l2));
        float e0 = __expf(l0 - m);
        float e1 = __expf(l1 - m);
        float e2 = __expf(l2 - m);
        float p  = e0 / (e0 + e1 + e2);
        float v  = 1.f / (1.f + __expf(-d));
        sval = p * v;
    }
    __syncthreads();

    const float s = sval;
    const float4 sv = make_float4(s, s, s, s);

    // Row 0: 400 floats = 100 float4, contiguous at slab start
    float4* o = reinterpret_cast<float4*>(out + (size_t)t * ROW);
    for (int i = threadIdx.x; i < HID / 4; i += TPB) {
        o[i] = sv;
    }
}

extern "C" void kernel_launch(void* const* d_in, const int* in_sizes, int n_in,
                              void* d_out, int out_size)
{
    const float* hid = (const float*)d_in[0];   // (1, 8192, 400)
    const float* W   = (const float*)d_in[1];   // (3, 400)
    const float* b   = (const float*)d_in[2];   // (3,)
    const float* D   = (const float*)d_in[3];   // (1, 400)
    float* out = (float*)d_out;                 // (1, 8192, 32, 400)

    // Zero the entire output (419 MB) via the driver's optimized fill path.
    cudaMemsetAsync(out, 0, (size_t)SEQ * ROW * sizeof(float));

    // Then overwrite row 0 of each slab with the computed scalar.
    top_kernel<<<SEQ, TPB>>>(hid, W, b, D, out);
}

// round 3
// speedup vs baseline: 1.0005x; 1.0005x over previous
#include <cuda_runtime.h>

#define HID 400
#define SEQ 8192
#define DEPTH 32
#define ROW (DEPTH * HID)          // 12800 floats per timestep slab
#define TPB 128                    // 4 warps = 4 timesteps per block

// One warp per timestep. Computes
//   s_t = softmax(h_t @ W^T + b)[0] * sigmoid(h_t @ D)
// and writes row 0 (400 floats) of slab t. Rows 1..31 are zeroed by the
// preceding memset node.
__global__ void __launch_bounds__(TPB)
top_kernel(const float* __restrict__ hid,
           const float* __restrict__ W,
           const float* __restrict__ b,
           const float* __restrict__ D,
           float* __restrict__ out)
{
    const int warp = threadIdx.x >> 5;
    const int lane = threadIdx.x & 31;
    const int t    = (blockIdx.x << 2) + warp;

    const float4* h4 = reinterpret_cast<const float4*>(hid + (size_t)t * HID);
    const float4* W4 = reinterpret_cast<const float4*>(W);
    const float4* D4 = reinterpret_cast<const float4*>(D);

    // 100 float4 per timestep; lane handles lane, lane+32, lane+64, (+96 if lane<4)
    float a0 = 0.f, a1 = 0.f, a2 = 0.f, ad = 0.f;
    #pragma unroll
    for (int k = 0; k < 4; k++) {
        int i = lane + (k << 5);
        if (i < HID / 4) {
            float4 x  = h4[i];
            float4 w0 = W4[i];
            float4 w1 = W4[HID / 4 + i];
            float4 w2 = W4[2 * (HID / 4) + i];
            float4 dd = D4[i];
            a0 += x.x * w0.x + x.y * w0.y + x.z * w0.z + x.w * w0.w;
            a1 += x.x * w1.x + x.y * w1.y + x.z * w1.z + x.w * w1.w;
            a2 += x.x * w2.x + x.y * w2.y + x.z * w2.z + x.w * w2.w;
            ad += x.x * dd.x + x.y * dd.y + x.z * dd.z + x.w * dd.w;
        }
    }

    // Butterfly reduce — every lane ends with the full sums.
    #pragma unroll
    for (int o = 16; o > 0; o >>= 1) {
        a0 += __shfl_xor_sync(0xffffffffu, a0, o);
        a1 += __shfl_xor_sync(0xffffffffu, a1, o);
        a2 += __shfl_xor_sync(0xffffffffu, a2, o);
        ad += __shfl_xor_sync(0xffffffffu, ad, o);
    }

    // Redundant per-lane epilogue (cheap MUFU ops, avoids any broadcast).
    float l0 = a0 + b[0], l1 = a1 + b[1], l2 = a2 + b[2];
    float m  = fmaxf(l0, fmaxf(l1, l2));
    float e0 = __expf(l0 - m);
    float e1 = __expf(l1 - m);
    float e2 = __expf(l2 - m);
    float p  = e0 / (e0 + e1 + e2);
    float v  = 1.f / (1.f + __expf(-ad));
    float s  = p * v;

    const float4 sv = make_float4(s, s, s, s);
    float4* o = reinterpret_cast<float4*>(out + (size_t)t * ROW);
    #pragma unroll
    for (int k = 0; k < 4; k++) {
        int i = lane + (k << 5);
        if (i < HID / 4) o[i] = sv;
    }
}

extern "C" void kernel_launch(void* const* d_in, const int* in_sizes, int n_in,
                              void* d_out, int out_size)
{
    const float* hid = (const float*)d_in[0];   // (1, 8192, 400)
    const float* W   = (const float*)d_in[1];   // (3, 400)
    const float* b   = (const float*)d_in[2];   // (3,)
    const float* D   = (const float*)d_in[3];   // (1, 400)
    float* out = (float*)d_out;                 // (1, 8192, 32, 400)

    // Zero the entire output (419 MB) via the driver's fill path (~7.4 TB/s).
    cudaMemsetAsync(out, 0, (size_t)SEQ * ROW * sizeof(float));

    // Overwrite row 0 of each slab with the computed scalar (26 MB traffic).
    top_kernel<<<SEQ / 4, TPB>>>(hid, W, b, D, out);
}

// round 4
// speedup vs baseline: 1.0009x; 1.0005x over previous
#include <cuda_runtime.h>

#define HID    400
#define SEQ    8192
#define DEPTH  32
#define ROWF4  (DEPTH * HID / 4)   // 3200 float4 per timestep slab
#define TOPF4  (HID / 4)           // 100 float4 in row 0
#define TPB    256
#define NWARP  (TPB / 32)

__global__ void __launch_bounds__(TPB, 8)
stack_kernel(const float* __restrict__ hid,
             const float* __restrict__ W,
             const float* __restrict__ b,
             const float* __restrict__ D,
             float* __restrict__ out)
{
    const int t   = blockIdx.x;
    const int tid = threadIdx.x;

    // ---- 1. Issue input loads immediately (tid < 100 hold one float4 each) ----
    float4 x, w0, w1, w2, dd;
    if (tid < TOPF4) {
        const float4* h4 = reinterpret_cast<const float4*>(hid + (size_t)t * HID);
        const float4* W4 = reinterpret_cast<const float4*>(W);
        const float4* D4 = reinterpret_cast<const float4*>(D);
        x  = h4[tid];
        w0 = W4[tid];
        w1 = W4[TOPF4 + tid];
        w2 = W4[2 * TOPF4 + tid];
        dd = D4[tid];
    }

    float4* o = reinterpret_cast<float4*>(out) + (size_t)t * ROWF4;
    const float4 zv = make_float4(0.f, 0.f, 0.f, 0.f);

    // ---- 2. Zero rows 1..31 (3100 float4) — depends on nothing, keeps DRAM hot ----
    #pragma unroll 4
    for (int i = TOPF4 + tid; i < ROWF4; i += TPB)
        o[i] = zv;

    // ---- 3. Reduction (loads completed long ago under the store shadow) ----
    float a0 = 0.f, a1 = 0.f, a2 = 0.f, ad = 0.f;
    if (tid < TOPF4) {
        a0 = x.x * w0.x + x.y * w0.y + x.z * w0.z + x.w * w0.w;
        a1 = x.x * w1.x + x.y * w1.y + x.z * w1.z + x.w * w1.w;
        a2 = x.x * w2.x + x.y * w2.y + x.z * w2.z + x.w * w2.w;
        ad = x.x * dd.x + x.y * dd.y + x.z * dd.z + x.w * dd.w;
    }

    #pragma unroll
    for (int off = 16; off > 0; off >>= 1) {
        a0 += __shfl_xor_sync(0xffffffffu, a0, off);
        a1 += __shfl_xor_sync(0xffffffffu, a1, off);
        a2 += __shfl_xor_sync(0xffffffffu, a2, off);
        ad += __shfl_xor_sync(0xffffffffu, ad, off);
    }

    __shared__ float sm[4][NWARP];
    const int w = tid >> 5;
    if ((tid & 31) == 0) {
        sm[0][w] = a0; sm[1][w] = a1; sm[2][w] = a2; sm[3][w] = ad;
    }
    __syncthreads();

    // Only warps 0..3 contributed nonzero data, but all 8 entries are valid (zeros).
    if (tid < TOPF4) {
        float l0 = b[0], l1 = b[1], l2 = b[2], d = 0.f;
        #pragma unroll
        for (int i = 0; i < NWARP; i++) {
            l0 += sm[0][i]; l1 += sm[1][i]; l2 += sm[2][i]; d += sm[3][i];
        }
        float m  = fmaxf(l0, fmaxf(l1, l2));
        float e0 = __expf(l0 - m);
        float e1 = __expf(l1 - m);
        float e2 = __expf(l2 - m);
        float p  = e0 / (e0 + e1 + e2);
        float v  = 1.f / (1.f + __expf(-d));
        float s  = p * v;

        // ---- 4. Row 0 store ----
        o[tid] = make_float4(s, s, s, s);
    }
}

extern "C" void kernel_launch(void* const* d_in, const int* in_sizes, int n_in,
                              void* d_out, int out_size)
{
    const float* hid = (const float*)d_in[0];   // (1, 8192, 400)
    const float* W   = (const float*)d_in[1];   // (3, 400)
    const float* b   = (const float*)d_in[2];   // (3,)
    const float* D   = (const float*)d_in[3];   // (1, 400)
    float* out = (float*)d_out;                 // (1, 8192, 32, 400)

    stack_kernel<<<SEQ, TPB>>>(hid, W, b, D, out);
}